// round 7
// baseline (speedup 1.0000x reference)
#include <cuda_runtime.h>
#include <math.h>

#define S_LEN   4096
#define D_DIM   512
#define K_TOT   1536          // 3 taps * 512
#define MAX_OUT 16384

#define BM 128
#define BN 64
#define BK 16
#define NCHUNK (K_TOT / BK)   // 96

typedef unsigned long long ull;

// ---------------- device scratch (16B aligned; no allocations allowed) ----------------
__device__ __align__(16) float g_Wt1[K_TOT * D_DIM];   // [(tap*512+i), o]
__device__ __align__(16) float g_Wt2[K_TOT * D_DIM];
__device__ __align__(16) float g_b1[S_LEN * D_DIM];    // conv out (reused by both convs)
__device__ __align__(16) float g_b2[S_LEN * D_DIM];    // ln1+relu out
__device__ __align__(16) int   g_dur[S_LEN];
__device__ __align__(16) int   g_cum[S_LEN];

// ---------------- weight transpose (both convs): w[o][i][k] -> Wt[(k*512+i)][o] ----------------
__global__ void transpose_w_kernel(const float* __restrict__ w1, const float* __restrict__ w2) {
    int idx = blockIdx.x * blockDim.x + threadIdx.x;
    const int n = K_TOT * D_DIM;
    if (idx >= 2 * n) return;
    const float* w  = (idx < n) ? w1 : w2;
    float*       wt = (idx < n) ? g_Wt1 : g_Wt2;
    int j  = (idx < n) ? idx : idx - n;
    int o  = j & 511;
    int ki = j >> 9;
    int i  = ki & 511;
    int k  = ki >> 9;
    wt[j] = w[o * 1536 + i * 3 + k];
}

// ---------------- conv-as-GEMM with packed f32x2 FMA (FFMA2) ----------------
// Y[s,o] = sum_{tap,i} X[s-1+tap, i] * Wt[(tap,i), o] + bias[o]
// BM=128, BN=64, BK=16, 128 threads, 8x8 microtile, rows packed in pairs (f32x2),
// double-buffered smem.
__global__ __launch_bounds__(128) void conv_gemm_kernel(
    const float* __restrict__ enc, const float* __restrict__ bias, int which) {
    const float* X  = which ? g_b2  : enc;
    const float* Wt = which ? g_Wt2 : g_Wt1;
    float*       Y  = g_b1;

    __shared__ __align__(16) float As[2][BK][BM + 4];   // [buf][k][m], padded
    __shared__ __align__(16) float Bs[2][BK][BN];       // [buf][k][n]

    const int bm  = blockIdx.y * BM;
    const int bn  = blockIdx.x * BN;
    const int tid = threadIdx.x;
    const int tx  = tid & 7;            // col group -> cols tx*8 .. tx*8+7
    const int ty  = tid >> 3;           // row group -> rows ty*8 .. ty*8+7
    const int ar  = tid;                // A loader: row 0..127 (16 floats of k each)
    const int br  = tid >> 3;           // B loader: k-row 0..15
    const int bc  = (tid & 7) * 8;      // B loader: col 0..56 (8 floats)

    ull acc[4][8];                      // [row-pair][col], f32x2 packed over 2 rows
    #pragma unroll
    for (int i = 0; i < 4; i++)
        #pragma unroll
        for (int j = 0; j < 8; j++) acc[i][j] = 0ull;

    float4 a_reg[4];
    float4 b_reg[2];

    // ---- chunk load into registers ----
    auto load_chunk = [&](int c) {
        const int k0  = c * BK;
        const int tap = k0 >> 9;                 // constant within chunk (512 % 16 == 0)
        const int i0  = k0 & 511;
        const int s   = bm + ar + tap - 1;
        if (s >= 0 && s < S_LEN) {
            const float4* xr = reinterpret_cast<const float4*>(X + (size_t)s * D_DIM + i0);
            a_reg[0] = xr[0]; a_reg[1] = xr[1]; a_reg[2] = xr[2]; a_reg[3] = xr[3];
        } else {
            const float4 z = make_float4(0.f, 0.f, 0.f, 0.f);
            a_reg[0] = z; a_reg[1] = z; a_reg[2] = z; a_reg[3] = z;
        }
        const float4* wr = reinterpret_cast<const float4*>(Wt + (size_t)(k0 + br) * D_DIM + bn + bc);
        b_reg[0] = wr[0]; b_reg[1] = wr[1];
    };

    auto store_chunk = [&](int buf) {
        #pragma unroll
        for (int q = 0; q < 4; q++) {
            As[buf][q * 4 + 0][ar] = a_reg[q].x;
            As[buf][q * 4 + 1][ar] = a_reg[q].y;
            As[buf][q * 4 + 2][ar] = a_reg[q].z;
            As[buf][q * 4 + 3][ar] = a_reg[q].w;
        }
        *reinterpret_cast<float4*>(&Bs[buf][br][bc])     = b_reg[0];
        *reinterpret_cast<float4*>(&Bs[buf][br][bc + 4]) = b_reg[1];
    };

    load_chunk(0);
    store_chunk(0);
    __syncthreads();

    for (int c = 0; c < NCHUNK; c++) {
        const int cur = c & 1;
        const bool have_next = (c + 1 < NCHUNK);
        if (have_next) load_chunk(c + 1);

        #pragma unroll
        for (int k = 0; k < BK; k++) {
            // 8 consecutive A rows -> 4 natural f32x2 pairs (two LDS.128)
            const ulonglong2* pa =
                reinterpret_cast<const ulonglong2*>(&As[cur][k][ty * 8]);
            ulonglong2 A01 = pa[0];
            ulonglong2 A23 = pa[1];
            ull a4[4] = {A01.x, A01.y, A23.x, A23.y};

            const float4 b0 = *reinterpret_cast<const float4*>(&Bs[cur][k][tx * 8]);
            const float4 b1 = *reinterpret_cast<const float4*>(&Bs[cur][k][tx * 8 + 4]);
            ull bb[8];
            asm("mov.b64 %0, {%1, %1};" : "=l"(bb[0]) : "f"(b0.x));
            asm("mov.b64 %0, {%1, %1};" : "=l"(bb[1]) : "f"(b0.y));
            asm("mov.b64 %0, {%1, %1};" : "=l"(bb[2]) : "f"(b0.z));
            asm("mov.b64 %0, {%1, %1};" : "=l"(bb[3]) : "f"(b0.w));
            asm("mov.b64 %0, {%1, %1};" : "=l"(bb[4]) : "f"(b1.x));
            asm("mov.b64 %0, {%1, %1};" : "=l"(bb[5]) : "f"(b1.y));
            asm("mov.b64 %0, {%1, %1};" : "=l"(bb[6]) : "f"(b1.z));
            asm("mov.b64 %0, {%1, %1};" : "=l"(bb[7]) : "f"(b1.w));

            #pragma unroll
            for (int rp = 0; rp < 4; rp++) {
                #pragma unroll
                for (int cc = 0; cc < 8; cc++) {
                    asm("fma.rn.f32x2 %0, %1, %2, %0;"
                        : "+l"(acc[rp][cc]) : "l"(a4[rp]), "l"(bb[cc]));
                }
            }
        }

        if (have_next) store_chunk(cur ^ 1);
        __syncthreads();
    }

    // ---- epilogue: unpack, add bias, store ----
    const float4 bb0 = *reinterpret_cast<const float4*>(bias + bn + tx * 8);
    const float4 bb1 = *reinterpret_cast<const float4*>(bias + bn + tx * 8 + 4);
    const float bcol[8] = {bb0.x, bb0.y, bb0.z, bb0.w, bb1.x, bb1.y, bb1.z, bb1.w};

    #pragma unroll
    for (int rp = 0; rp < 4; rp++) {
        float lo[8], hi[8];
        #pragma unroll
        for (int cc = 0; cc < 8; cc++) {
            asm("mov.b64 {%0, %1}, %2;" : "=f"(lo[cc]), "=f"(hi[cc]) : "l"(acc[rp][cc]));
            lo[cc] += bcol[cc];
            hi[cc] += bcol[cc];
        }
        const int r0 = bm + ty * 8 + rp * 2;
        float4* y0 = reinterpret_cast<float4*>(Y + (size_t)r0 * D_DIM + bn + tx * 8);
        float4* y1 = reinterpret_cast<float4*>(Y + (size_t)(r0 + 1) * D_DIM + bn + tx * 8);
        y0[0] = make_float4(lo[0], lo[1], lo[2], lo[3]);
        y0[1] = make_float4(lo[4], lo[5], lo[6], lo[7]);
        y1[0] = make_float4(hi[0], hi[1], hi[2], hi[3]);
        y1[1] = make_float4(hi[4], hi[5], hi[6], hi[7]);
    }
}

__device__ __forceinline__ float warp_allsum(float v) {
    #pragma unroll
    for (int o = 16; o > 0; o >>= 1) v += __shfl_xor_sync(0xffffffffu, v, o);
    return v;
}

// ---------------- LN1 + ReLU:  g_b1 -> g_b2   (128 threads / row) ----------------
__global__ __launch_bounds__(128) void ln_relu_kernel(
    const float* __restrict__ G, const float* __restrict__ Bt) {
    const int s   = blockIdx.x;
    const int tid = threadIdx.x;
    __shared__ float red1[4], red2[4];

    float4 v = reinterpret_cast<const float4*>(g_b1 + (size_t)s * D_DIM)[tid];
    float p = warp_allsum(v.x + v.y + v.z + v.w);
    const int lane = tid & 31, wid = tid >> 5;
    if (lane == 0) red1[wid] = p;
    __syncthreads();
    const float mean = (red1[0] + red1[1] + red1[2] + red1[3]) * (1.0f / 512.0f);

    float dx = v.x - mean, dy = v.y - mean, dz = v.z - mean, dw = v.w - mean;
    float q = warp_allsum(dx * dx + dy * dy + dz * dz + dw * dw);
    if (lane == 0) red2[wid] = q;
    __syncthreads();
    const float var = (red2[0] + red2[1] + red2[2] + red2[3]) * (1.0f / 512.0f);
    const float inv = rsqrtf(var + 1e-5f);

    const float4 gv = reinterpret_cast<const float4*>(G)[tid];
    const float4 bv = reinterpret_cast<const float4*>(Bt)[tid];
    float4 o;
    o.x = fmaxf(0.f, dx * inv * gv.x + bv.x);
    o.y = fmaxf(0.f, dy * inv * gv.y + bv.y);
    o.z = fmaxf(0.f, dz * inv * gv.z + bv.z);
    o.w = fmaxf(0.f, dw * inv * gv.w + bv.w);
    reinterpret_cast<float4*>(g_b2 + (size_t)s * D_DIM)[tid] = o;
}

// ---------------- LN2 + ReLU + linear(512->1) + ReLU + floor(+0.5): g_b1 -> g_dur ----------------
__global__ __launch_bounds__(128) void ln2_lin_kernel(
    const float* __restrict__ G, const float* __restrict__ Bt,
    const float* __restrict__ LW, const float* __restrict__ LB) {
    const int s   = blockIdx.x;
    const int tid = threadIdx.x;
    __shared__ float red1[4], red2[4], red3[4];

    float4 v = reinterpret_cast<const float4*>(g_b1 + (size_t)s * D_DIM)[tid];
    float p = warp_allsum(v.x + v.y + v.z + v.w);
    const int lane = tid & 31, wid = tid >> 5;
    if (lane == 0) red1[wid] = p;
    __syncthreads();
    const float mean = (red1[0] + red1[1] + red1[2] + red1[3]) * (1.0f / 512.0f);

    float dx = v.x - mean, dy = v.y - mean, dz = v.z - mean, dw = v.w - mean;
    float q = warp_allsum(dx * dx + dy * dy + dz * dz + dw * dw);
    if (lane == 0) red2[wid] = q;
    __syncthreads();
    const float var = (red2[0] + red2[1] + red2[2] + red2[3]) * (1.0f / 512.0f);
    const float inv = rsqrtf(var + 1e-5f);

    const float4 gv = reinterpret_cast<const float4*>(G)[tid];
    const float4 bv = reinterpret_cast<const float4*>(Bt)[tid];
    float ox = fmaxf(0.f, dx * inv * gv.x + bv.x);
    float oy = fmaxf(0.f, dy * inv * gv.y + bv.y);
    float oz = fmaxf(0.f, dz * inv * gv.z + bv.z);
    float ow = fmaxf(0.f, dw * inv * gv.w + bv.w);

    const float4 lw = reinterpret_cast<const float4*>(LW)[tid];
    float d = warp_allsum(ox * lw.x + oy * lw.y + oz * lw.z + ow * lw.w);
    if (lane == 0) red3[wid] = d;
    __syncthreads();
    if (tid == 0) {
        float pred = fmaxf(0.f, red3[0] + red3[1] + red3[2] + red3[3] + LB[0]);
        g_dur[s] = (int)floorf(pred + 0.5f);
    }
}

// ---------------- cumsum over 4096 ints, single block of 512 threads ----------------
__global__ __launch_bounds__(512) void cumsum_kernel() {
    __shared__ int wsum[16];
    const int tid  = threadIdx.x;
    const int lane = tid & 31, wid = tid >> 5;

    int vals[8];
    int s = 0;
    #pragma unroll
    for (int j = 0; j < 8; j++) { s += g_dur[tid * 8 + j]; vals[j] = s; }

    int x = s;
    #pragma unroll
    for (int off = 1; off < 32; off <<= 1) {
        int y = __shfl_up_sync(0xffffffffu, x, off);
        if (lane >= off) x += y;
    }
    if (lane == 31) wsum[wid] = x;
    __syncthreads();
    if (wid == 0 && lane < 16) {
        int w = wsum[lane];
        #pragma unroll
        for (int off = 1; off < 16; off <<= 1) {
            int y = __shfl_up_sync(0x0000ffffu, w, off);
            if (lane >= off) w += y;
        }
        wsum[lane] = w;
    }
    __syncthreads();
    const int offset = (wid > 0 ? wsum[wid - 1] : 0) + (x - s);
    #pragma unroll
    for (int j = 0; j < 8; j++) g_cum[tid * 8 + j] = vals[j] + offset;
}

// ---------------- expansion: one block per output frame t (fixed-trip bisection) ----------------
__global__ __launch_bounds__(128) void expand_kernel(
    const float* __restrict__ enc, float* __restrict__ out) {
    const int t = blockIdx.x;
    __shared__ int s_idx;
    __shared__ int s_valid;
    if (threadIdx.x == 0) {
        const int total = g_cum[S_LEN - 1];
        int lo = 0;
        #pragma unroll
        for (int step = 2048; step >= 1; step >>= 1) {
            int cand = lo + step;
            if (cand <= S_LEN && g_cum[cand - 1] <= t) lo = cand;
        }
        s_idx = (lo < S_LEN - 1) ? lo : (S_LEN - 1);
        s_valid = (t < total) ? 1 : 0;
    }
    __syncthreads();
    float4 val = make_float4(0.f, 0.f, 0.f, 0.f);
    if (s_valid)
        val = reinterpret_cast<const float4*>(enc + (size_t)s_idx * D_DIM)[threadIdx.x];
    reinterpret_cast<float4*>(out + (size_t)t * D_DIM)[threadIdx.x] = val;
}

// ---------------- optional output_pos tail ----------------
__global__ void pos_tail_kernel(float* __restrict__ out, int base, int n) {
    int i = blockIdx.x * blockDim.x + threadIdx.x;
    if (i < n) out[base + i] = (float)((i % MAX_OUT) + 1);
}

// ---------------- launch ----------------
extern "C" void kernel_launch(void* const* d_in, const int* in_sizes, int n_in,
                              void* d_out, int out_size) {
    const float* enc = (const float*)d_in[0];
    const float* c1w = (const float*)d_in[1];
    const float* c1b = (const float*)d_in[2];
    const float* g1  = (const float*)d_in[3];
    const float* b1  = (const float*)d_in[4];
    const float* c2w = (const float*)d_in[5];
    const float* c2b = (const float*)d_in[6];
    const float* g2  = (const float*)d_in[7];
    const float* b2  = (const float*)d_in[8];
    const float* lw  = (const float*)d_in[9];
    const float* lb  = (const float*)d_in[10];
    float* out = (float*)d_out;

    {
        int n = 2 * K_TOT * D_DIM;
        transpose_w_kernel<<<(n + 255) / 256, 256>>>(c1w, c2w);
    }

    dim3 ggrid(D_DIM / BN, S_LEN / BM);   // (8, 32)
    conv_gemm_kernel<<<ggrid, 128>>>(enc, c1b, 0);     // conv1: enc  -> g_b1
    ln_relu_kernel<<<S_LEN, 128>>>(g1, b1);            // ln1:  g_b1 -> g_b2
    conv_gemm_kernel<<<ggrid, 128>>>(enc, c2b, 1);     // conv2: g_b2 -> g_b1
    ln2_lin_kernel<<<S_LEN, 128>>>(g2, b2, lw, lb);    // ln2+linear -> g_dur
    cumsum_kernel<<<1, 512>>>();
    int frames = out_size / D_DIM;
    if (frames > MAX_OUT) frames = MAX_OUT;
    if (frames > 0)
        expand_kernel<<<frames, 128>>>(enc, out);
    int base = frames * D_DIM;
    if (out_size > base) {
        int extra = out_size - base;
        pos_tail_kernel<<<(extra + 255) / 256, 256>>>(out, base, extra);
    }
}